// round 13
// baseline (speedup 1.0000x reference)
#include <cuda_runtime.h>
#include <cuda_bf16.h>
#include <mma.h>
#include <cstdint>
#include <cstddef>
#include <math_constants.h>

using namespace nvcuda;

// ---------------- problem constants ----------------
#define NN 50000
#define NE 25000
#define PE 400000
#define ME 800000
#define PN 400000
#define MN 800000
#define NNP 50048
#define NEP 25088

static __host__ __device__ constexpr size_t alup(size_t x) { return (x + 255) & ~size_t(255); }

// ---------------- scratch layout ----------------
constexpr size_t O_NODEH = 0;
constexpr size_t O_NODEV = O_NODEH + alup((size_t)NNP * 128 * 4);
constexpr size_t O_NODES = O_NODEV + alup((size_t)NNP * 128 * 4);
constexpr size_t O_DEGA  = O_NODES + alup((size_t)NN * 4 * 4);
constexpr size_t O_DINVA = O_DEGA  + alup((size_t)PE * 4);
constexpr size_t O_SEGPA = O_DINVA + alup((size_t)PE * 4);
constexpr size_t O_CNTA  = O_SEGPA + alup((size_t)(NE + 1) * 4);
constexpr size_t O_OFFA  = O_CNTA  + alup((size_t)NE * 4);
constexpr size_t O_CURA  = O_OFFA  + alup((size_t)(NE + 1) * 4);
constexpr size_t O_SRTGA = O_CURA  + alup((size_t)NE * 4);
constexpr size_t O_SRTWA = O_SRTGA + alup((size_t)ME * 4);
constexpr size_t O_POOLA = O_SRTWA + alup((size_t)ME * 4);
constexpr size_t O_EDGEX = O_POOLA + alup((size_t)NE * 128 * 4);
constexpr size_t O_EDGEH = O_EDGEX + alup((size_t)NEP * 256 * 4);
constexpr size_t O_EDGEV = O_EDGEH + alup((size_t)NEP * 128 * 4);
constexpr size_t O_EDGES = O_EDGEV + alup((size_t)NEP * 128 * 4);
constexpr size_t O_DEGB  = O_EDGES + alup((size_t)NE * 4 * 4);
constexpr size_t O_DINVB = O_DEGB  + alup((size_t)PN * 4);
constexpr size_t O_SEGPB = O_DINVB + alup((size_t)PN * 4);
constexpr size_t O_CNTB  = O_SEGPB + alup((size_t)(NN + 1) * 4);
constexpr size_t O_OFFB  = O_CNTB  + alup((size_t)NN * 4);
constexpr size_t O_CURB  = O_OFFB  + alup((size_t)(NN + 1) * 4);
constexpr size_t O_SRTGB = O_CURB  + alup((size_t)NN * 4);
constexpr size_t O_SRTWB = O_SRTGB + alup((size_t)MN * 4);
constexpr size_t O_POOLB = O_SRTWB + alup((size_t)MN * 4);
constexpr size_t O_NODEO = O_POOLB + alup((size_t)NN * 128 * 4);
constexpr size_t O_WKSA  = O_NODEO + alup((size_t)NNP * 256 * 4);
constexpr size_t O_WKSB  = O_WKSA  + alup((size_t)128 * 4 * 4);
constexpr size_t O_INCLA = O_WKSB  + alup((size_t)256 * 4 * 4);
constexpr size_t O_BSUMA = O_INCLA + alup((size_t)NE * 4);
constexpr size_t O_INCLB = O_BSUMA + alup((size_t)64 * 4);
constexpr size_t O_BSUMB = O_INCLB + alup((size_t)NN * 4);
constexpr size_t O_WAH   = O_BSUMB + alup((size_t)64 * 4);
constexpr size_t O_WAL   = O_WAH   + alup((size_t)256 * 128 * 2);
constexpr size_t O_WO1H  = O_WAL   + alup((size_t)256 * 128 * 2);
constexpr size_t O_WO1L  = O_WO1H  + alup((size_t)128 * 128 * 2);
constexpr size_t O_WBH   = O_WO1L  + alup((size_t)128 * 128 * 2);
constexpr size_t O_WBL   = O_WBH   + alup((size_t)256 * 256 * 2);
constexpr size_t O_WO2H  = O_WBL   + alup((size_t)256 * 256 * 2);
constexpr size_t O_WO2L  = O_WO2H  + alup((size_t)128 * 128 * 2);
constexpr size_t O_WCH   = O_WO2L  + alup((size_t)128 * 128 * 2);
constexpr size_t O_WCL   = O_WCH   + alup((size_t)64 * 256 * 2);
constexpr size_t SCRATCH_TOTAL = O_WCL + alup((size_t)64 * 256 * 2);

__device__ __align__(256) unsigned char g_scratch[SCRATCH_TOTAL];

// ---------------- shared device helpers ----------------
__device__ __forceinline__ void cp16(void* smem_dst, const void* gsrc) {
    uint32_t sa = (uint32_t)__cvta_generic_to_shared(smem_dst);
    asm volatile("cp.async.cg.shared.global [%0], [%1], 16;" :: "r"(sa), "l"(gsrc));
}
#define CP_COMMIT() asm volatile("cp.async.commit_group;" ::: "memory")
#define CP_WAIT0()  asm volatile("cp.async.wait_group 0;" ::: "memory")

__device__ __forceinline__ void pack_hilo(const float* vv, uint4& hp, uint4& lp) {
    ushort hs[8], ls[8];
    #pragma unroll
    for (int q = 0; q < 8; q++) {
        __nv_bfloat16 h = __float2bfloat16(vv[q]);
        hs[q] = __bfloat16_as_ushort(h);
        ls[q] = __bfloat16_as_ushort(__float2bfloat16(vv[q] - __bfloat162float(h)));
    }
    hp.x = hs[0] | ((uint32_t)hs[1] << 16); hp.y = hs[2] | ((uint32_t)hs[3] << 16);
    hp.z = hs[4] | ((uint32_t)hs[5] << 16); hp.w = hs[6] | ((uint32_t)hs[7] << 16);
    lp.x = ls[0] | ((uint32_t)ls[1] << 16); lp.y = ls[2] | ((uint32_t)ls[3] << 16);
    lp.z = ls[4] | ((uint32_t)ls[5] << 16); lp.w = ls[6] | ((uint32_t)ls[7] << 16);
}

__device__ __forceinline__ void cvt_store(const float* W, int N, int i,
                                          __nv_bfloat16* hi, __nv_bfloat16* lo,
                                          int n_off, int ldK) {
    int k = i / N, n = i % N;
    float v = W[i];
    __nv_bfloat16 h = __float2bfloat16(v);
    float r = v - __bfloat162float(h);
    hi[(size_t)(n_off + n) * ldK + k] = h;
    lo[(size_t)(n_off + n) * ldK + k] = __float2bfloat16(r);
}

__device__ __forceinline__ void fold_one(const float* Wk, const float* seed,
                                         float* Wks, int i) {
    int f = i >> 2, h = i & 3;
    float s = 0.f;
    #pragma unroll
    for (int d = 0; d < 32; d++) s += Wk[(size_t)f * 128 + h * 32 + d] * seed[h * 32 + d];
    Wks[i] = s * 0.17677669529663687f;
}

__device__ __forceinline__ void rowdot_body(const float* __restrict__ X,
                                            const float* __restrict__ Wks,
                                            float* __restrict__ out,
                                            int row, int K, int lane) {
    const float* x = X + (size_t)row * K;
    float a0 = 0, a1 = 0, a2 = 0, a3 = 0;
    for (int f0 = lane * 4; f0 < K; f0 += 128) {
        float4 xv = *(const float4*)&x[f0];
        float4 w0 = *(const float4*)&Wks[(size_t)(f0 + 0) * 4];
        float4 w1 = *(const float4*)&Wks[(size_t)(f0 + 1) * 4];
        float4 w2 = *(const float4*)&Wks[(size_t)(f0 + 2) * 4];
        float4 w3 = *(const float4*)&Wks[(size_t)(f0 + 3) * 4];
        a0 += xv.x * w0.x + xv.y * w1.x + xv.z * w2.x + xv.w * w3.x;
        a1 += xv.x * w0.y + xv.y * w1.y + xv.z * w2.y + xv.w * w3.y;
        a2 += xv.x * w0.z + xv.y * w1.z + xv.z * w2.z + xv.w * w3.z;
        a3 += xv.x * w0.w + xv.y * w1.w + xv.z * w2.w + xv.w * w3.w;
    }
    #pragma unroll
    for (int o = 16; o; o >>= 1) {
        a0 += __shfl_xor_sync(0xffffffffu, a0, o);
        a1 += __shfl_xor_sync(0xffffffffu, a1, o);
        a2 += __shfl_xor_sync(0xffffffffu, a2, o);
        a3 += __shfl_xor_sync(0xffffffffu, a3, o);
    }
    if (lane == 0) {
        float* o4 = out + (size_t)row * 4;
        o4[0] = a0; o4[1] = a1; o4[2] = a2; o4[3] = a3;
    }
}

__device__ __forceinline__ void seg_start_one(const int* __restrict__ batch, int P, int s,
                                              int* __restrict__ segP) {
    int lo = 0, hi = P;
    while (lo < hi) {
        int mid = (lo + hi) >> 1;
        if (batch[mid] < s) lo = mid + 1; else hi = mid;
    }
    segP[s] = lo;
}

// ---------------- misc0 ----------------
constexpr int M0_R1 = PE;
constexpr int M0_R2 = M0_R1 + PN;
constexpr int M0_R3 = M0_R2 + NE;
constexpr int M0_R4 = M0_R3 + NN;
constexpr int M0_R5 = M0_R4 + NE + 1;
constexpr int M0_R6 = M0_R5 + NN + 1;
constexpr int M0_R7 = M0_R6 + 148992;

__global__ void misc0_k(
    const int* __restrict__ eb_batch, const int* __restrict__ nb_batch,
    int* degA, int* cntA, int* curA, int* degB, int* cntB, int* curB,
    int* segPA, int* segPB,
    const float* __restrict__ W1, const float* __restrict__ Wv1, const float* __restrict__ Wo1,
    const float* __restrict__ W2, const float* __restrict__ Wv2, const float* __restrict__ Wo2,
    const float* __restrict__ clsW,
    const float* __restrict__ Wk1, const float* __restrict__ sd1,
    const float* __restrict__ Wk2, const float* __restrict__ sd2,
    __nv_bfloat16* WAh, __nv_bfloat16* WAl, __nv_bfloat16* WO1h, __nv_bfloat16* WO1l,
    __nv_bfloat16* WBh, __nv_bfloat16* WBl, __nv_bfloat16* WO2h, __nv_bfloat16* WO2l,
    __nv_bfloat16* WCh, __nv_bfloat16* WCl, float* WksA, float* WksB) {
    int i = blockIdx.x * blockDim.x + threadIdx.x;
    if (i < M0_R1)      degA[i] = 0;
    else if (i < M0_R2) degB[i - M0_R1] = 0;
    else if (i < M0_R3) { int j = i - M0_R2; cntA[j] = 0; curA[j] = 0; }
    else if (i < M0_R4) { int j = i - M0_R3; cntB[j] = 0; curB[j] = 0; }
    else if (i < M0_R5) seg_start_one(eb_batch, PE, i - M0_R4, segPA);
    else if (i < M0_R6) seg_start_one(nb_batch, PN, i - M0_R5, segPB);
    else if (i < M0_R7) {
        int j = i - M0_R6;
        if (j < 16384)       cvt_store(W1,  128, j, WAh, WAl, 0, 128);
        else if (j < 32768)  cvt_store(Wv1, 128, j - 16384, WAh, WAl, 128, 128);
        else if (j < 49152)  cvt_store(Wo1, 128, j - 32768, WO1h, WO1l, 0, 128);
        else if (j < 81920)  cvt_store(W2,  128, j - 49152, WBh, WBl, 0, 256);
        else if (j < 114688) cvt_store(Wv2, 128, j - 81920, WBh, WBl, 128, 256);
        else if (j < 131072) cvt_store(Wo2, 128, j - 114688, WO2h, WO2l, 0, 128);
        else if (j < 141312) cvt_store(clsW, 40, j - 131072, WCh, WCl, 0, 256);
        else if (j < 147456) {
            int q = j - 141312;
            size_t p = (size_t)(40 + q / 256) * 256 + (q % 256);
            WCh[p] = __float2bfloat16(0.f);
            WCl[p] = __float2bfloat16(0.f);
        }
        else if (j < 147968) fold_one(Wk1, sd1, WksA, j - 147456);
        else                 fold_one(Wk2, sd2, WksB, j - 147968);
    }
}

// ---------------- WMMA bf16 GEMM, 2-stage pipelined (hi/lo 3-term split) ----------------
struct XArgs {
    const int* dstA; const int* batA; int* degA; int* cntA;
    const int* dstB; const int* batB; int* degB; int* cntB;
    const float* X; const float* Wks; float* S; int M;
};

template<int KC, int NT, int MODE, int EXTRA>
__global__ void __launch_bounds__(256, 2)
wgemm_k(const float* __restrict__ A, int M,
        const __nv_bfloat16* __restrict__ Bhi, const __nv_bfloat16* __restrict__ Blo,
        float* __restrict__ out0, float* __restrict__ out1, int ldc,
        int gemmGX, XArgs xa) {
    if (EXTRA && blockIdx.x >= gemmGX) {
        if (blockIdx.y != 0) return;
        int id = (blockIdx.x - gemmGX) * 256 + threadIdx.x;
        if (EXTRA == 1) {
            if (id < ME) {
                int d = xa.dstA[id];
                atomicAdd(&xa.degA[d], 1);
                atomicAdd(&xa.cntA[xa.batA[d]], 1);
            } else if (id < ME + MN) {
                id -= ME;
                int d = xa.dstB[id];
                atomicAdd(&xa.degB[d], 1);
                atomicAdd(&xa.cntB[xa.batB[d]], 1);
            }
        } else {
            int gw = id >> 5;
            if (gw < xa.M) rowdot_body(xa.X, xa.Wks, xa.S, gw, 256, threadIdx.x & 31);
        }
        return;
    }

    constexpr int K = KC * 16;
    constexpr int WN = NT / 2;
    constexpr int NTI = WN / 16;
    constexpr int STG_E = (256 + 2 * NT) * 24;

    extern __shared__ char smc[];
    __nv_bfloat16* sb = (__nv_bfloat16*)smc;

    int tid = threadIdx.x;
    int wid = tid >> 5;
    int wm = wid >> 1, wn = wid & 1;
    int row0 = blockIdx.x * 128;
    int col0 = blockIdx.y * NT;

    int ar = tid >> 1, akk = (tid & 1) * 8;
    int gr = row0 + ar;
    const float* aptr = (gr < M) ? (A + (size_t)gr * K + akk) : nullptr;

    wmma::fragment<wmma::accumulator, 16, 16, 16, float> acc[2][NTI];
    #pragma unroll
    for (int m = 0; m < 2; m++)
        #pragma unroll
        for (int n = 0; n < NTI; n++) wmma::fill_fragment(acc[m][n], 0.0f);

    float4 pv0, pv1;
    {
        pv0 = make_float4(0.f, 0.f, 0.f, 0.f); pv1 = pv0;
        if (aptr) { pv0 = *(const float4*)aptr; pv1 = *(const float4*)(aptr + 4); }
        __nv_bfloat16* sBh0 = sb + 256 * 24;
        __nv_bfloat16* sBl0 = sBh0 + NT * 24;
        for (int i = tid; i < NT * 2; i += 256) {
            int n = i >> 1, kk = (i & 1) * 8;
            size_t g = (size_t)(col0 + n) * K + kk;
            cp16(&sBh0[n * 24 + kk], Bhi + g);
            cp16(&sBl0[n * 24 + kk], Blo + g);
        }
        CP_COMMIT();
        float vv[8] = {pv0.x, pv0.y, pv0.z, pv0.w, pv1.x, pv1.y, pv1.z, pv1.w};
        uint4 hp, lp;
        pack_hilo(vv, hp, lp);
        *(uint4*)&sb[ar * 24 + akk] = hp;
        *(uint4*)&sb[128 * 24 + ar * 24 + akk] = lp;
    }

    for (int kc = 0; kc < KC; kc++) {
        int buf = kc & 1;
        __nv_bfloat16* sAh = sb + buf * STG_E;
        __nv_bfloat16* sAl = sAh + 128 * 24;
        __nv_bfloat16* sBh = sAl + 128 * 24;
        __nv_bfloat16* sBl = sBh + NT * 24;
        CP_WAIT0();
        __syncthreads();

        if (kc + 1 < KC) {
            pv0 = make_float4(0.f, 0.f, 0.f, 0.f); pv1 = pv0;
            if (aptr) {
                const float* ap = aptr + (kc + 1) * 16;
                pv0 = *(const float4*)ap; pv1 = *(const float4*)(ap + 4);
            }
            __nv_bfloat16* nBh = sb + (buf ^ 1) * STG_E + 256 * 24;
            __nv_bfloat16* nBl = nBh + NT * 24;
            for (int i = tid; i < NT * 2; i += 256) {
                int n = i >> 1, kk = (i & 1) * 8;
                size_t g = (size_t)(col0 + n) * K + (kc + 1) * 16 + kk;
                cp16(&nBh[n * 24 + kk], Bhi + g);
                cp16(&nBl[n * 24 + kk], Blo + g);
            }
            CP_COMMIT();
        }

        wmma::fragment<wmma::matrix_a, 16, 16, 16, __nv_bfloat16, wmma::row_major> ah[2], al[2];
        #pragma unroll
        for (int m = 0; m < 2; m++) {
            wmma::load_matrix_sync(ah[m], sAh + (wm * 32 + m * 16) * 24, 24);
            wmma::load_matrix_sync(al[m], sAl + (wm * 32 + m * 16) * 24, 24);
        }
        #pragma unroll
        for (int n = 0; n < NTI; n++) {
            wmma::fragment<wmma::matrix_b, 16, 16, 16, __nv_bfloat16, wmma::col_major> bh, bl;
            wmma::load_matrix_sync(bh, sBh + (wn * WN + n * 16) * 24, 24);
            wmma::load_matrix_sync(bl, sBl + (wn * WN + n * 16) * 24, 24);
            #pragma unroll
            for (int m = 0; m < 2; m++) {
                wmma::mma_sync(acc[m][n], ah[m], bh, acc[m][n]);
                wmma::mma_sync(acc[m][n], ah[m], bl, acc[m][n]);
                wmma::mma_sync(acc[m][n], al[m], bh, acc[m][n]);
            }
        }

        if (kc + 1 < KC) {
            __nv_bfloat16* nAh = sb + (buf ^ 1) * STG_E;
            __nv_bfloat16* nAl = nAh + 128 * 24;
            float vv[8] = {pv0.x, pv0.y, pv0.z, pv0.w, pv1.x, pv1.y, pv1.z, pv1.w};
            uint4 hp, lp;
            pack_hilo(vv, hp, lp);
            *(uint4*)&nAh[ar * 24 + akk] = hp;
            *(uint4*)&nAl[ar * 24 + akk] = lp;
        }
    }
    __syncthreads();

    #pragma unroll
    for (int m = 0; m < 2; m++) {
        int gr0 = row0 + wm * 32 + m * 16;
        #pragma unroll
        for (int n = 0; n < NTI; n++) {
            int gc = col0 + wn * WN + n * 16;
            if (MODE == 1) {
                #pragma unroll
                for (int t = 0; t < acc[m][n].num_elements; t++)
                    acc[m][n].x[t] = fmaxf(acc[m][n].x[t], 0.f);
                wmma::store_matrix_sync(out0 + (size_t)gr0 * ldc + gc, acc[m][n],
                                        ldc, wmma::mem_row_major);
            } else {
                float* dst = (gc < 128) ? (out0 + (size_t)gr0 * 128 + gc)
                                        : (out1 + (size_t)gr0 * 128 + gc - 128);
                wmma::store_matrix_sync(dst, acc[m][n], 128, wmma::mem_row_major);
            }
        }
    }
}

// ---------------- fused Wo2 + classifier + log-softmax ----------------
constexpr int CLS_PIPE = 49152;
constexpr int CLS_SMEM = CLS_PIPE + 128 * 132 * 4;  // 116736

__global__ void __launch_bounds__(256, 1)
cls_fused_k(const float* __restrict__ poolB, const float* __restrict__ convB, int M,
            const __nv_bfloat16* __restrict__ Wo2h, const __nv_bfloat16* __restrict__ Wo2l,
            const __nv_bfloat16* __restrict__ WCh, const __nv_bfloat16* __restrict__ WCl,
            const float* __restrict__ clsb, float* __restrict__ out) {
    extern __shared__ char smc[];
    __nv_bfloat16* sb = (__nv_bfloat16*)smc;
    float* T = (float*)(smc + CLS_PIPE);

    int tid = threadIdx.x;
    int wid = tid >> 5;
    int wm = wid >> 1, wn = wid & 1;
    int row0 = blockIdx.x * 128;
    int ar = tid >> 1, akk = (tid & 1) * 8;
    int gr = row0 + ar;

    // ===== phase 1: T = relu(poolB @ Wo2), NT=128, K=128 =====
    {
        constexpr int NT = 128, KC = 8, K = 128, WN = 64, NTI = 4;
        constexpr int STG_E = (256 + 2 * NT) * 24;
        const float* aptr = (gr < M) ? (poolB + (size_t)gr * K + akk) : nullptr;

        wmma::fragment<wmma::accumulator, 16, 16, 16, float> acc[2][NTI];
        #pragma unroll
        for (int m = 0; m < 2; m++)
            #pragma unroll
            for (int n = 0; n < NTI; n++) wmma::fill_fragment(acc[m][n], 0.0f);

        float4 pv0, pv1;
        {
            pv0 = make_float4(0.f, 0.f, 0.f, 0.f); pv1 = pv0;
            if (aptr) { pv0 = *(const float4*)aptr; pv1 = *(const float4*)(aptr + 4); }
            __nv_bfloat16* sBh0 = sb + 256 * 24;
            __nv_bfloat16* sBl0 = sBh0 + NT * 24;
            for (int i = tid; i < NT * 2; i += 256) {
                int n = i >> 1, kk = (i & 1) * 8;
                size_t g = (size_t)n * K + kk;
                cp16(&sBh0[n * 24 + kk], Wo2h + g);
                cp16(&sBl0[n * 24 + kk], Wo2l + g);
            }
            CP_COMMIT();
            float vv[8] = {pv0.x, pv0.y, pv0.z, pv0.w, pv1.x, pv1.y, pv1.z, pv1.w};
            uint4 hp, lp;
            pack_hilo(vv, hp, lp);
            *(uint4*)&sb[ar * 24 + akk] = hp;
            *(uint4*)&sb[128 * 24 + ar * 24 + akk] = lp;
        }

        for (int kc = 0; kc < KC; kc++) {
            int buf = kc & 1;
            __nv_bfloat16* sAh = sb + buf * STG_E;
            __nv_bfloat16* sAl = sAh + 128 * 24;
            __nv_bfloat16* sBh = sAl + 128 * 24;
            __nv_bfloat16* sBl = sBh + NT * 24;
            CP_WAIT0();
            __syncthreads();

            if (kc + 1 < KC) {
                pv0 = make_float4(0.f, 0.f, 0.f, 0.f); pv1 = pv0;
                if (aptr) {
                    const float* ap = aptr + (kc + 1) * 16;
                    pv0 = *(const float4*)ap; pv1 = *(const float4*)(ap + 4);
                }
                __nv_bfloat16* nBh = sb + (buf ^ 1) * STG_E + 256 * 24;
                __nv_bfloat16* nBl = nBh + NT * 24;
                for (int i = tid; i < NT * 2; i += 256) {
                    int n = i >> 1, kk = (i & 1) * 8;
                    size_t g = (size_t)n * K + (kc + 1) * 16 + kk;
                    cp16(&nBh[n * 24 + kk], Wo2h + g);
                    cp16(&nBl[n * 24 + kk], Wo2l + g);
                }
                CP_COMMIT();
            }

            wmma::fragment<wmma::matrix_a, 16, 16, 16, __nv_bfloat16, wmma::row_major> ah[2], al[2];
            #pragma unroll
            for (int m = 0; m < 2; m++) {
                wmma::load_matrix_sync(ah[m], sAh + (wm * 32 + m * 16) * 24, 24);
                wmma::load_matrix_sync(al[m], sAl + (wm * 32 + m * 16) * 24, 24);
            }
            #pragma unroll
            for (int n = 0; n < NTI; n++) {
                wmma::fragment<wmma::matrix_b, 16, 16, 16, __nv_bfloat16, wmma::col_major> bh, bl;
                wmma::load_matrix_sync(bh, sBh + (wn * WN + n * 16) * 24, 24);
                wmma::load_matrix_sync(bl, sBl + (wn * WN + n * 16) * 24, 24);
                #pragma unroll
                for (int m = 0; m < 2; m++) {
                    wmma::mma_sync(acc[m][n], ah[m], bh, acc[m][n]);
                    wmma::mma_sync(acc[m][n], ah[m], bl, acc[m][n]);
                    wmma::mma_sync(acc[m][n], al[m], bh, acc[m][n]);
                }
            }

            if (kc + 1 < KC) {
                __nv_bfloat16* nAh = sb + (buf ^ 1) * STG_E;
                __nv_bfloat16* nAl = nAh + 128 * 24;
                float vv[8] = {pv0.x, pv0.y, pv0.z, pv0.w, pv1.x, pv1.y, pv1.z, pv1.w};
                uint4 hp, lp;
                pack_hilo(vv, hp, lp);
                *(uint4*)&nAh[ar * 24 + akk] = hp;
                *(uint4*)&nAl[ar * 24 + akk] = lp;
            }
        }
        __syncthreads();

        #pragma unroll
        for (int m = 0; m < 2; m++)
            #pragma unroll
            for (int n = 0; n < NTI; n++) {
                #pragma unroll
                for (int t = 0; t < acc[m][n].num_elements; t++)
                    acc[m][n].x[t] = fmaxf(acc[m][n].x[t], 0.f);
                wmma::store_matrix_sync(T + (wm * 32 + m * 16) * 132 + wn * WN + n * 16,
                                        acc[m][n], 132, wmma::mem_row_major);
            }
        __syncthreads();
    }

    // ===== phase 2: logits = convB@Wc[0:128] + T@Wc[128:256], NT=64, K=256 =====
    {
        constexpr int NT = 64, KC = 16, K = 256, WN = 32, NTI = 2;
        constexpr int STG_E = (256 + 2 * NT) * 24;

        wmma::fragment<wmma::accumulator, 16, 16, 16, float> acc[2][NTI];
        #pragma unroll
        for (int m = 0; m < 2; m++)
            #pragma unroll
            for (int n = 0; n < NTI; n++) wmma::fill_fragment(acc[m][n], 0.0f);

        {
            __nv_bfloat16* sBh0 = sb + 256 * 24;
            __nv_bfloat16* sBl0 = sBh0 + NT * 24;
            for (int i = tid; i < NT * 2; i += 256) {
                int n = i >> 1, kk = (i & 1) * 8;
                size_t g = (size_t)n * K + kk;
                cp16(&sBh0[n * 24 + kk], WCh + g);
                cp16(&sBl0[n * 24 + kk], WCl + g);
            }
            CP_COMMIT();
        }

        for (int kc = 0; kc < KC; kc++) {
            int buf = kc & 1;
            __nv_bfloat16* sAh = sb + buf * STG_E;
            __nv_bfloat16* sAl = sAh + 128 * 24;
            __nv_bfloat16* sBh = sAl + 128 * 24;
            __nv_bfloat16* sBl = sBh + NT * 24;
            CP_WAIT0();
            __syncthreads();

            if (kc + 1 < KC) {
                __nv_bfloat16* nBh = sb + (buf ^ 1) * STG_E + 256 * 24;
                __nv_bfloat16* nBl = nBh + NT * 24;
                for (int i = tid; i < NT * 2; i += 256) {
                    int n = i >> 1, kk = (i & 1) * 8;
                    size_t g = (size_t)n * K + (kc + 1) * 16 + kk;
                    cp16(&nBh[n * 24 + kk], WCh + g);
                    cp16(&nBl[n * 24 + kk], WCl + g);
                }
                CP_COMMIT();
            }

            {
                float vv[8];
                if (kc < 8) {
                    float4 v0 = make_float4(0.f, 0.f, 0.f, 0.f), v1 = v0;
                    if (gr < M) {
                        const float* ap = convB + (size_t)gr * 128 + kc * 16 + akk;
                        v0 = *(const float4*)ap; v1 = *(const float4*)(ap + 4);
                    }
                    vv[0] = v0.x; vv[1] = v0.y; vv[2] = v0.z; vv[3] = v0.w;
                    vv[4] = v1.x; vv[5] = v1.y; vv[6] = v1.z; vv[7] = v1.w;
                } else {
                    const float* tp = T + ar * 132 + (kc - 8) * 16 + akk;
                    #pragma unroll
                    for (int q = 0; q < 8; q++) vv[q] = tp[q];
                }
                uint4 hp, lp;
                pack_hilo(vv, hp, lp);
                *(uint4*)&sAh[ar * 24 + akk] = hp;
                *(uint4*)&sAl[ar * 24 + akk] = lp;
            }
            __syncthreads();

            wmma::fragment<wmma::matrix_a, 16, 16, 16, __nv_bfloat16, wmma::row_major> ah[2], al[2];
            #pragma unroll
            for (int m = 0; m < 2; m++) {
                wmma::load_matrix_sync(ah[m], sAh + (wm * 32 + m * 16) * 24, 24);
                wmma::load_matrix_sync(al[m], sAl + (wm * 32 + m * 16) * 24, 24);
            }
            #pragma unroll
            for (int n = 0; n < NTI; n++) {
                wmma::fragment<wmma::matrix_b, 16, 16, 16, __nv_bfloat16, wmma::col_major> bh, bl;
                wmma::load_matrix_sync(bh, sBh + (wn * WN + n * 16) * 24, 24);
                wmma::load_matrix_sync(bl, sBl + (wn * WN + n * 16) * 24, 24);
                #pragma unroll
                for (int m = 0; m < 2; m++) {
                    wmma::mma_sync(acc[m][n], ah[m], bh, acc[m][n]);
                    wmma::mma_sync(acc[m][n], ah[m], bl, acc[m][n]);
                    wmma::mma_sync(acc[m][n], al[m], bh, acc[m][n]);
                }
            }
        }
        __syncthreads();

        float* stg = (float*)sb;
        #pragma unroll
        for (int m = 0; m < 2; m++)
            #pragma unroll
            for (int n = 0; n < NTI; n++)
                wmma::store_matrix_sync(stg + (wm * 32 + m * 16) * 68 + wn * WN + n * 16,
                                        acc[m][n], 68, wmma::mem_row_major);
        __syncthreads();
        if (tid < 128) {
            int r = row0 + tid;
            if (r < M) {
                const float* row = stg + tid * 68;
                float v[40];
                float mx = -CUDART_INF_F;
                #pragma unroll
                for (int c = 0; c < 40; c++) { v[c] = row[c] + clsb[c]; mx = fmaxf(mx, v[c]); }
                float s = 0.f;
                #pragma unroll
                for (int c = 0; c < 40; c++) s += expf(v[c] - mx);
                float lse = mx + logf(s);
                #pragma unroll
                for (int c = 0; c < 40; c += 4) {
                    float4 f = make_float4(v[c] - lse, v[c+1] - lse, v[c+2] - lse, v[c+3] - lse);
                    *(float4*)&out[(size_t)r * 40 + c] = f;
                }
            }
        }
    }
}

// ---------------- misc1 / fin2 / scatter ----------------
constexpr int NBA = (NE + 1023) / 1024;
constexpr int NBB = (NN + 1023) / 1024;
constexpr int DINV_B = (PE + PN + 1023) / 1024;
constexpr int RDA_B = (NN + 31) / 32;

__device__ __forceinline__ void scan_body(const int* __restrict__ cnt, int n,
                                          int* __restrict__ incl, int* __restrict__ bsums,
                                          int b) {
    __shared__ int sm[1024];
    int i = b * 1024 + threadIdx.x;
    int v = (i < n) ? cnt[i] : 0;
    sm[threadIdx.x] = v;
    __syncthreads();
    for (int o = 1; o < 1024; o <<= 1) {
        int t = (threadIdx.x >= o) ? sm[threadIdx.x - o] : 0;
        __syncthreads();
        sm[threadIdx.x] += t;
        __syncthreads();
    }
    if (i < n) incl[i] = sm[threadIdx.x];
    if (threadIdx.x == 1023) bsums[b] = sm[1023];
}

__global__ void misc1_k(const int* __restrict__ cntA, int* inclA, int* bsumA,
                        const int* __restrict__ cntB, int* inclB, int* bsumB,
                        const int* __restrict__ degA, float* dinvA,
                        const int* __restrict__ degB, float* dinvB,
                        const float* __restrict__ X, const float* __restrict__ Wks,
                        float* S) {
    int b = blockIdx.x;
    if (b < NBA) { scan_body(cntA, NE, inclA, bsumA, b); return; }
    b -= NBA;
    if (b < NBB) { scan_body(cntB, NN, inclB, bsumB, b); return; }
    b -= NBB;
    if (b < DINV_B) {
        int i = b * 1024 + threadIdx.x;
        if (i < PE) dinvA[i] = rsqrtf((float)(degA[i] + 1));
        else if (i < PE + PN) dinvB[i - PE] = rsqrtf((float)(degB[i - PE] + 1));
        return;
    }
    b -= DINV_B;
    int gw = b * 32 + (threadIdx.x >> 5);
    if (gw < NN) rowdot_body(X, Wks, S, gw, 128, threadIdx.x & 31);
}

__global__ void fin2_k(const int* __restrict__ inclA, const int* __restrict__ bsumA, int* offA,
                       const int* __restrict__ inclB, const int* __restrict__ bsumB, int* offB) {
    __shared__ int pfx;
    int b = blockIdx.x;
    if (b < NBA) {
        if (threadIdx.x == 0) {
            int s = 0;
            for (int t = 0; t < b; t++) s += bsumA[t];
            pfx = s;
        }
        __syncthreads();
        int i = b * 1024 + threadIdx.x;
        if (i < NE) offA[i + 1] = inclA[i] + pfx;
        if (i == 0) offA[0] = 0;
    } else {
        b -= NBA;
        if (threadIdx.x == 0) {
            int s = 0;
            for (int t = 0; t < b; t++) s += bsumB[t];
            pfx = s;
        }
        __syncthreads();
        int i = b * 1024 + threadIdx.x;
        if (i < NN) offB[i + 1] = inclB[i] + pfx;
        if (i == 0) offB[0] = 0;
    }
}

__device__ __forceinline__ void scatter_one(const int* src, const int* dst, const int* batch,
                                            const int* map, const float* dinv, const int* off,
                                            int* cursor, int i, int* outG, float* outW) {
    int d = dst[i];
    int s = batch[d];
    int pos = off[s] + atomicAdd(&cursor[s], 1);
    int sc = src[i];
    outG[pos] = map[sc];
    outW[pos] = dinv[sc] * dinv[d];
}

__global__ void scatterA_k(const int* eb_ei, const int* eb_batch, const int* eb_map,
                           const float* dinvA, const int* offA, int* curA,
                           int* srtGA, float* srtWA) {
    int i = blockIdx.x * blockDim.x + threadIdx.x;
    if (i < ME)
        scatter_one(eb_ei, eb_ei + ME, eb_batch, eb_map, dinvA, offA, curA, i, srtGA, srtWA);
}

// ---------------- fused per-segment: GCN-conv mean + PMA softmax pool ----------------
struct SBArgs {
    const int* src; const int* dst; const int* batch; const int* map;
    const float* dinv; const int* off; int* cur; int* outG; float* outW;
};

__global__ void __launch_bounds__(256)
seg_fused_k(const float* __restrict__ H, const float* __restrict__ V,
            const float* __restrict__ S4, const int* __restrict__ map,
            const float* __restrict__ dinv,
            const int* __restrict__ segP, const int* __restrict__ eOff,
            const int* __restrict__ sG, const float* __restrict__ sW,
            const float* __restrict__ bias,
            float* __restrict__ outConv, int ldOut,
            float* __restrict__ pooled, int S,
            int gxSeg, SBArgs sb2) {
    if (sb2.dst && blockIdx.x >= gxSeg) {
        int i = (blockIdx.x - gxSeg) * 256 + threadIdx.x;
        if (i < MN)
            scatter_one(sb2.src, sb2.dst, sb2.batch, sb2.map, sb2.dinv, sb2.off,
                        sb2.cur, i, sb2.outG, sb2.outW);
        return;
    }

    int w = (blockIdx.x * blockDim.x + threadIdx.x) >> 5;
    if (w >= S) return;
    int lane = threadIdx.x & 31;
    int h = lane >> 3;
    int sub = lane & 7;
    int s = w;
    const float4* H4 = (const float4*)H;
    const float4* V4 = (const float4*)V;

    int p0 = segP[s], p1 = segP[s + 1];
    int e0 = eOff[s], e1 = eOff[s + 1];

    float4 acc = make_float4(0.f, 0.f, 0.f, 0.f);
    int j = e0;
    for (; j + 7 < e1; j += 8) {
        int g[8];
        float wt[8];
        #pragma unroll
        for (int q = 0; q < 8; q++) { g[q] = sG[j + q]; wt[q] = sW[j + q]; }
        float4 hv[8];
        #pragma unroll
        for (int q = 0; q < 8; q++) hv[q] = H4[(size_t)g[q] * 32 + lane];
        #pragma unroll
        for (int q = 0; q < 8; q++) {
            acc.x += hv[q].x * wt[q];
            acc.y += hv[q].y * wt[q];
            acc.z += hv[q].z * wt[q];
            acc.w += hv[q].w * wt[q];
        }
    }
    for (; j < e1; j++) {
        int g = sG[j]; float wt = sW[j];
        float4 hv = H4[(size_t)g * 32 + lane];
        acc.x += hv.x * wt; acc.y += hv.y * wt; acc.z += hv.z * wt; acc.w += hv.w * wt;
    }

    float m = -CUDART_INF_F;
    for (int p = p0 + sub; p < p1; p += 8)
        m = fmaxf(m, S4[(size_t)map[p] * 4 + h]);
    #pragma unroll
    for (int o = 1; o < 8; o <<= 1)
        m = fmaxf(m, __shfl_xor_sync(0xffffffffu, m, o));

    float den = 0.f;
    float4 pv = make_float4(0.f, 0.f, 0.f, 0.f);
    int p = p0;
    for (; p + 3 < p1; p += 4) {
        int g[4];
        float wt[4], e[4];
        #pragma unroll
        for (int q = 0; q < 4; q++) {
            g[q] = map[p + q];
            float d = dinv[p + q];
            wt[q] = d * d;
        }
        float4 hv[4], vv[4];
        #pragma unroll
        for (int q = 0; q < 4; q++) {
            hv[q] = H4[(size_t)g[q] * 32 + lane];
            vv[q] = V4[(size_t)g[q] * 32 + lane];
        }
        #pragma unroll
        for (int q = 0; q < 4; q++) {
            e[q] = __expf(S4[(size_t)g[q] * 4 + h] - m);
            den += e[q];
        }
        #pragma unroll
        for (int q = 0; q < 4; q++) {
            acc.x += hv[q].x * wt[q];  pv.x += vv[q].x * e[q];
            acc.y += hv[q].y * wt[q];  pv.y += vv[q].y * e[q];
            acc.z += hv[q].z * wt[q];  pv.z += vv[q].z * e[q];
            acc.w += hv[q].w * wt[q];  pv.w += vv[q].w * e[q];
        }
    }
    for (; p < p1; p++) {
        int g = map[p];
        float d = dinv[p];
        float wt = d * d;
        float e = __expf(S4[(size_t)g * 4 + h] - m);
        den += e;
        float4 hv = H4[(size_t)g * 32 + lane];
        float4 vv = V4[(size_t)g * 32 + lane];
        acc.x += hv.x * wt;  pv.x += vv.x * e;
        acc.y += hv.y * wt;  pv.y += vv.y * e;
        acc.z += hv.z * wt;  pv.z += vv.z * e;
        acc.w += hv.w * wt;  pv.w += vv.w * e;
    }

    int cnt = p1 - p0;
    float4 ob;
    if (cnt > 0) {
        float inv = 1.f / (float)cnt;
        float4 b4 = *(const float4*)&bias[lane * 4];
        ob.x = fmaxf(acc.x * inv + b4.x, 0.f);
        ob.y = fmaxf(acc.y * inv + b4.y, 0.f);
        ob.z = fmaxf(acc.z * inv + b4.z, 0.f);
        ob.w = fmaxf(acc.w * inv + b4.w, 0.f);
    } else {
        ob = make_float4(0.f, 0.f, 0.f, 0.f);
    }
    *(float4*)&outConv[(size_t)s * ldOut + lane * 4] = ob;

    float dn = 1.f / fmaxf(den, 1e-9f);
    float4 op;
    op.x = pv.x * dn; op.y = pv.y * dn; op.z = pv.z * dn; op.w = pv.w * dn;
    if (cnt == 0) op = make_float4(0.f, 0.f, 0.f, 0.f);
    *(float4*)&pooled[(size_t)s * 128 + lane * 4] = op;
}

// ---------------- orchestration (single stream, graph-safe) ----------------
static inline int cdiv(int a, int b) { return (a + b - 1) / b; }

extern "C" void kernel_launch(void* const* d_in, const int* in_sizes, int n_in,
                              void* d_out, int out_size) {
    (void)in_sizes; (void)n_in; (void)out_size;
    const float* node_x  = (const float*)d_in[0];
    const int* eb_map    = (const int*)d_in[1];
    const int* eb_ei     = (const int*)d_in[2];
    const int* eb_batch  = (const int*)d_in[3];
    const int* nb_map    = (const int*)d_in[4];
    const int* nb_ei     = (const int*)d_in[5];
    const int* nb_batch  = (const int*)d_in[6];
    const float* W1   = (const float*)d_in[7];
    const float* b1   = (const float*)d_in[8];
    const float* Wk1  = (const float*)d_in[9];
    const float* Wv1  = (const float*)d_in[10];
    const float* sd1  = (const float*)d_in[11];
    const float* Wo1  = (const float*)d_in[12];
    const float* W2   = (const float*)d_in[13];
    const float* b2   = (const float*)d_in[14];
    const float* Wk2  = (const float*)d_in[15];
    const float* Wv2  = (const float*)d_in[16];
    const float* sd2  = (const float*)d_in[17];
    const float* Wo2  = (const float*)d_in[18];
    const float* clsW = (const float*)d_in[19];
    const float* clsb = (const float*)d_in[20];
    float* out = (float*)d_out;

    void* basep = nullptr;
    cudaGetSymbolAddress(&basep, g_scratch);
    char* base = (char*)basep;
    float* nodeH  = (float*)(base + O_NODEH);
    float* nodeV  = (float*)(base + O_NODEV);
    float* nodeS  = (float*)(base + O_NODES);
    int*   degA   = (int*)  (base + O_DEGA);
    float* dinvA  = (float*)(base + O_DINVA);
    int*   segPA  = (int*)  (base + O_SEGPA);
    int*   cntA   = (int*)  (base + O_CNTA);
    int*   offA   = (int*)  (base + O_OFFA);
    int*   curA   = (int*)  (base + O_CURA);
    int*   srtGA  = (int*)  (base + O_SRTGA);
    float* srtWA  = (float*)(base + O_SRTWA);
    float* poolA  = (float*)(base + O_POOLA);
    float* edgeX  = (float*)(base + O_EDGEX);
    float* edgeH  = (float*)(base + O_EDGEH);
    float* edgeV  = (float*)(base + O_EDGEV);
    float* edgeS  = (float*)(base + O_EDGES);
    int*   degB   = (int*)  (base + O_DEGB);
    float* dinvB  = (float*)(base + O_DINVB);
    int*   segPB  = (int*)  (base + O_SEGPB);
    int*   cntB   = (int*)  (base + O_CNTB);
    int*   offB   = (int*)  (base + O_OFFB);
    int*   curB   = (int*)  (base + O_CURB);
    int*   srtGB  = (int*)  (base + O_SRTGB);
    float* srtWB  = (float*)(base + O_SRTWB);
    float* poolB  = (float*)(base + O_POOLB);
    float* nodeO  = (float*)(base + O_NODEO);
    float* WksA   = (float*)(base + O_WKSA);
    float* WksB   = (float*)(base + O_WKSB);
    int*   inclA  = (int*)  (base + O_INCLA);
    int*   bsumA  = (int*)  (base + O_BSUMA);
    int*   inclB  = (int*)  (base + O_INCLB);
    int*   bsumB  = (int*)  (base + O_BSUMB);
    __nv_bfloat16* WAh  = (__nv_bfloat16*)(base + O_WAH);
    __nv_bfloat16* WAl  = (__nv_bfloat16*)(base + O_WAL);
    __nv_bfloat16* WO1h = (__nv_bfloat16*)(base + O_WO1H);
    __nv_bfloat16* WO1l = (__nv_bfloat16*)(base + O_WO1L);
    __nv_bfloat16* WBh  = (__nv_bfloat16*)(base + O_WBH);
    __nv_bfloat16* WBl  = (__nv_bfloat16*)(base + O_WBL);
    __nv_bfloat16* WO2h = (__nv_bfloat16*)(base + O_WO2H);
    __nv_bfloat16* WO2l = (__nv_bfloat16*)(base + O_WO2L);
    __nv_bfloat16* WCh  = (__nv_bfloat16*)(base + O_WCH);
    __nv_bfloat16* WCl  = (__nv_bfloat16*)(base + O_WCL);

    constexpr int SMAB128 = 2 * (256 + 2 * 128) * 24 * 2;  // 49152
    cudaFuncSetAttribute(wgemm_k<8, 128, 0, 1>,  cudaFuncAttributeMaxDynamicSharedMemorySize, SMAB128);
    cudaFuncSetAttribute(wgemm_k<8, 128, 1, 0>,  cudaFuncAttributeMaxDynamicSharedMemorySize, SMAB128);
    cudaFuncSetAttribute(wgemm_k<16, 128, 0, 2>, cudaFuncAttributeMaxDynamicSharedMemorySize, SMAB128);
    cudaFuncSetAttribute(cls_fused_k, cudaFuncAttributeMaxDynamicSharedMemorySize, CLS_SMEM);

    XArgs xnone = {};
    XArgs xdeg = { eb_ei + ME, eb_batch, degA, cntA,
                   nb_ei + MN, nb_batch, degB, cntB,
                   nullptr, nullptr, nullptr, 0 };
    XArgs xrdB = { nullptr, nullptr, nullptr, nullptr,
                   nullptr, nullptr, nullptr, nullptr,
                   edgeX, WksB, edgeS, NE };
    SBArgs sbNone = {};
    SBArgs sbB = { nb_ei, nb_ei + MN, nb_batch, nb_map, dinvB, offB, curB, srtGB, srtWB };

    // L1: init + seg_starts + all weight prep
    misc0_k<<<cdiv(M0_R7, 256), 256>>>(eb_batch, nb_batch,
                                       degA, cntA, curA, degB, cntB, curB, segPA, segPB,
                                       W1, Wv1, Wo1, W2, Wv2, Wo2, clsW,
                                       Wk1, sd1, Wk2, sd2,
                                       WAh, WAl, WO1h, WO1l, WBh, WBl,
                                       WO2h, WO2l, WCh, WCl, WksA, WksB);

    // L2: stage-A GEMM  ∥  degcount (both stages)
    {
        int gx = cdiv(NN, 128);
        int extra = cdiv(ME + MN, 256);
        dim3 g(gx + extra, 2);
        wgemm_k<8, 128, 0, 1><<<g, 256, SMAB128>>>(node_x, NN, WAh, WAl,
                                                   nodeH, nodeV, 0, gx, xdeg);
    }

    // L3: both scans + both dinv + rowdot4-A
    misc1_k<<<NBA + NBB + DINV_B + RDA_B, 1024>>>(cntA, inclA, bsumA, cntB, inclB, bsumB,
                                                  degA, dinvA, degB, dinvB,
                                                  node_x, WksA, nodeS);
    // L4: finalize offsets
    fin2_k<<<NBA + NBB, 1024>>>(inclA, bsumA, offA, inclB, bsumB, offB);

    // L5: scatter A only
    scatterA_k<<<cdiv(ME, 256), 256>>>(eb_ei, eb_batch, eb_map, dinvA, offA, curA,
                                       srtGA, srtWA);

    // L6: stage-A fused segment kernel  ∥  scatter B piggyback
    {
        int gxSeg = cdiv(NE * 32, 256);
        int extra = cdiv(MN, 256);
        seg_fused_k<<<gxSeg + extra, 256>>>(nodeH, nodeV, nodeS, eb_map, dinvA, segPA, offA,
                                            srtGA, srtWA, b1, edgeX, 256, poolA, NE,
                                            gxSeg, sbB);
    }
    // L7: Wo1
    {
        int gx = cdiv(NE, 128);
        dim3 g(gx, 1);
        wgemm_k<8, 128, 1, 0><<<g, 256, SMAB128>>>(poolA, NE, WO1h, WO1l,
                                                   edgeX + 128, nullptr, 256, gx, xnone);
    }

    // L8: stage-B GEMM  ∥  rowdot4-B
    {
        int gx = cdiv(NE, 128);
        int extra = cdiv(NE * 32, 256);
        dim3 g(gx + extra, 2);
        wgemm_k<16, 128, 0, 2><<<g, 256, SMAB128>>>(edgeX, NE, WBh, WBl,
                                                    edgeH, edgeV, 0, gx, xrdB);
    }

    // L9: stage-B fused segment kernel (conv written densely, ld 128)
    {
        int gxSeg = cdiv(NN * 32, 256);
        seg_fused_k<<<gxSeg, 256>>>(edgeH, edgeV, edgeS, nb_map, dinvB, segPB, offB,
                                    srtGB, srtWB, b2, nodeO, 128, poolB, NN,
                                    gxSeg, sbNone);
    }

    // L10: fused Wo2 + classifier + log-softmax
    cls_fused_k<<<cdiv(NN, 128), 256, CLS_SMEM>>>(poolB, nodeO, NN,
                                                  WO2h, WO2l, WCh, WCl, clsb, out);
}

// round 14
// speedup vs baseline: 1.0360x; 1.0360x over previous
#include <cuda_runtime.h>
#include <cuda_bf16.h>
#include <mma.h>
#include <cstdint>
#include <cstddef>
#include <math_constants.h>

using namespace nvcuda;

// ---------------- problem constants ----------------
#define NN 50000
#define NE 25000
#define PE 400000
#define ME 800000
#define PN 400000
#define MN 800000
#define NNP 50048
#define NEP 25088

static __host__ __device__ constexpr size_t alup(size_t x) { return (x + 255) & ~size_t(255); }

// ---------------- scratch layout ----------------
constexpr size_t O_NODEH = 0;
constexpr size_t O_NODEV = O_NODEH + alup((size_t)NNP * 128 * 4);
constexpr size_t O_NODES = O_NODEV + alup((size_t)NNP * 128 * 4);
constexpr size_t O_DEGA  = O_NODES + alup((size_t)NN * 4 * 4);
constexpr size_t O_DINVA = O_DEGA  + alup((size_t)PE * 4);
constexpr size_t O_SEGPA = O_DINVA + alup((size_t)PE * 4);
constexpr size_t O_CNTA  = O_SEGPA + alup((size_t)(NE + 1) * 4);
constexpr size_t O_OFFA  = O_CNTA  + alup((size_t)NE * 4);
constexpr size_t O_CURA  = O_OFFA  + alup((size_t)(NE + 1) * 4);
constexpr size_t O_SRTGA = O_CURA  + alup((size_t)NE * 4);
constexpr size_t O_SRTWA = O_SRTGA + alup((size_t)ME * 4);
constexpr size_t O_POOLA = O_SRTWA + alup((size_t)ME * 4);
constexpr size_t O_EDGEX = O_POOLA + alup((size_t)NE * 128 * 4);
constexpr size_t O_EDGEH = O_EDGEX + alup((size_t)NEP * 256 * 4);
constexpr size_t O_EDGEV = O_EDGEH + alup((size_t)NEP * 128 * 4);
constexpr size_t O_EDGES = O_EDGEV + alup((size_t)NEP * 128 * 4);
constexpr size_t O_DEGB  = O_EDGES + alup((size_t)NE * 4 * 4);
constexpr size_t O_DINVB = O_DEGB  + alup((size_t)PN * 4);
constexpr size_t O_SEGPB = O_DINVB + alup((size_t)PN * 4);
constexpr size_t O_CNTB  = O_SEGPB + alup((size_t)(NN + 1) * 4);
constexpr size_t O_OFFB  = O_CNTB  + alup((size_t)NN * 4);
constexpr size_t O_CURB  = O_OFFB  + alup((size_t)(NN + 1) * 4);
constexpr size_t O_SRTGB = O_CURB  + alup((size_t)NN * 4);
constexpr size_t O_SRTWB = O_SRTGB + alup((size_t)MN * 4);
constexpr size_t O_POOLB = O_SRTWB + alup((size_t)MN * 4);
constexpr size_t O_NODEO = O_POOLB + alup((size_t)NN * 128 * 4);
constexpr size_t O_WKSA  = O_NODEO + alup((size_t)NNP * 256 * 4);
constexpr size_t O_WKSB  = O_WKSA  + alup((size_t)128 * 4 * 4);
constexpr size_t O_INCLA = O_WKSB  + alup((size_t)256 * 4 * 4);
constexpr size_t O_BSUMA = O_INCLA + alup((size_t)NE * 4);
constexpr size_t O_INCLB = O_BSUMA + alup((size_t)64 * 4);
constexpr size_t O_BSUMB = O_INCLB + alup((size_t)NN * 4);
constexpr size_t O_WAH   = O_BSUMB + alup((size_t)64 * 4);
constexpr size_t O_WAL   = O_WAH   + alup((size_t)256 * 128 * 2);
constexpr size_t O_WO1H  = O_WAL   + alup((size_t)256 * 128 * 2);
constexpr size_t O_WO1L  = O_WO1H  + alup((size_t)128 * 128 * 2);
constexpr size_t O_WBH   = O_WO1L  + alup((size_t)128 * 128 * 2);
constexpr size_t O_WBL   = O_WBH   + alup((size_t)256 * 256 * 2);
constexpr size_t O_WO2H  = O_WBL   + alup((size_t)256 * 256 * 2);
constexpr size_t O_WO2L  = O_WO2H  + alup((size_t)128 * 128 * 2);
constexpr size_t O_WCH   = O_WO2L  + alup((size_t)128 * 128 * 2);
constexpr size_t O_WCL   = O_WCH   + alup((size_t)64 * 256 * 2);
constexpr size_t SCRATCH_TOTAL = O_WCL + alup((size_t)64 * 256 * 2);

__device__ __align__(256) unsigned char g_scratch[SCRATCH_TOTAL];

// ---------------- shared device helpers ----------------
__device__ __forceinline__ void cp16(void* smem_dst, const void* gsrc) {
    uint32_t sa = (uint32_t)__cvta_generic_to_shared(smem_dst);
    asm volatile("cp.async.cg.shared.global [%0], [%1], 16;" :: "r"(sa), "l"(gsrc));
}
#define CP_COMMIT() asm volatile("cp.async.commit_group;" ::: "memory")
#define CP_WAIT0()  asm volatile("cp.async.wait_group 0;" ::: "memory")

__device__ __forceinline__ void pack_hilo(const float* vv, uint4& hp, uint4& lp) {
    ushort hs[8], ls[8];
    #pragma unroll
    for (int q = 0; q < 8; q++) {
        __nv_bfloat16 h = __float2bfloat16(vv[q]);
        hs[q] = __bfloat16_as_ushort(h);
        ls[q] = __bfloat16_as_ushort(__float2bfloat16(vv[q] - __bfloat162float(h)));
    }
    hp.x = hs[0] | ((uint32_t)hs[1] << 16); hp.y = hs[2] | ((uint32_t)hs[3] << 16);
    hp.z = hs[4] | ((uint32_t)hs[5] << 16); hp.w = hs[6] | ((uint32_t)hs[7] << 16);
    lp.x = ls[0] | ((uint32_t)ls[1] << 16); lp.y = ls[2] | ((uint32_t)ls[3] << 16);
    lp.z = ls[4] | ((uint32_t)ls[5] << 16); lp.w = ls[6] | ((uint32_t)ls[7] << 16);
}

__device__ __forceinline__ void cvt_store(const float* W, int N, int i,
                                          __nv_bfloat16* hi, __nv_bfloat16* lo,
                                          int n_off, int ldK) {
    int k = i / N, n = i % N;
    float v = W[i];
    __nv_bfloat16 h = __float2bfloat16(v);
    float r = v - __bfloat162float(h);
    hi[(size_t)(n_off + n) * ldK + k] = h;
    lo[(size_t)(n_off + n) * ldK + k] = __float2bfloat16(r);
}

__device__ __forceinline__ void fold_one(const float* Wk, const float* seed,
                                         float* Wks, int i) {
    int f = i >> 2, h = i & 3;
    float s = 0.f;
    #pragma unroll
    for (int d = 0; d < 32; d++) s += Wk[(size_t)f * 128 + h * 32 + d] * seed[h * 32 + d];
    Wks[i] = s * 0.17677669529663687f;
}

__device__ __forceinline__ void rowdot_body(const float* __restrict__ X,
                                            const float* __restrict__ Wks,
                                            float* __restrict__ out,
                                            int row, int K, int lane) {
    const float* x = X + (size_t)row * K;
    float a0 = 0, a1 = 0, a2 = 0, a3 = 0;
    for (int f0 = lane * 4; f0 < K; f0 += 128) {
        float4 xv = *(const float4*)&x[f0];
        float4 w0 = *(const float4*)&Wks[(size_t)(f0 + 0) * 4];
        float4 w1 = *(const float4*)&Wks[(size_t)(f0 + 1) * 4];
        float4 w2 = *(const float4*)&Wks[(size_t)(f0 + 2) * 4];
        float4 w3 = *(const float4*)&Wks[(size_t)(f0 + 3) * 4];
        a0 += xv.x * w0.x + xv.y * w1.x + xv.z * w2.x + xv.w * w3.x;
        a1 += xv.x * w0.y + xv.y * w1.y + xv.z * w2.y + xv.w * w3.y;
        a2 += xv.x * w0.z + xv.y * w1.z + xv.z * w2.z + xv.w * w3.z;
        a3 += xv.x * w0.w + xv.y * w1.w + xv.z * w2.w + xv.w * w3.w;
    }
    #pragma unroll
    for (int o = 16; o; o >>= 1) {
        a0 += __shfl_xor_sync(0xffffffffu, a0, o);
        a1 += __shfl_xor_sync(0xffffffffu, a1, o);
        a2 += __shfl_xor_sync(0xffffffffu, a2, o);
        a3 += __shfl_xor_sync(0xffffffffu, a3, o);
    }
    if (lane == 0) {
        float* o4 = out + (size_t)row * 4;
        o4[0] = a0; o4[1] = a1; o4[2] = a2; o4[3] = a3;
    }
}

__device__ __forceinline__ void seg_start_one(const int* __restrict__ batch, int P, int s,
                                              int* __restrict__ segP) {
    int lo = 0, hi = P;
    while (lo < hi) {
        int mid = (lo + hi) >> 1;
        if (batch[mid] < s) lo = mid + 1; else hi = mid;
    }
    segP[s] = lo;
}

// ---------------- misc0 ----------------
constexpr int M0_R1 = PE;
constexpr int M0_R2 = M0_R1 + PN;
constexpr int M0_R3 = M0_R2 + NE;
constexpr int M0_R4 = M0_R3 + NN;
constexpr int M0_R5 = M0_R4 + NE + 1;
constexpr int M0_R6 = M0_R5 + NN + 1;
constexpr int M0_R7 = M0_R6 + 148992;

__global__ void misc0_k(
    const int* __restrict__ eb_batch, const int* __restrict__ nb_batch,
    int* degA, int* cntA, int* curA, int* degB, int* cntB, int* curB,
    int* segPA, int* segPB,
    const float* __restrict__ W1, const float* __restrict__ Wv1, const float* __restrict__ Wo1,
    const float* __restrict__ W2, const float* __restrict__ Wv2, const float* __restrict__ Wo2,
    const float* __restrict__ clsW,
    const float* __restrict__ Wk1, const float* __restrict__ sd1,
    const float* __restrict__ Wk2, const float* __restrict__ sd2,
    __nv_bfloat16* WAh, __nv_bfloat16* WAl, __nv_bfloat16* WO1h, __nv_bfloat16* WO1l,
    __nv_bfloat16* WBh, __nv_bfloat16* WBl, __nv_bfloat16* WO2h, __nv_bfloat16* WO2l,
    __nv_bfloat16* WCh, __nv_bfloat16* WCl, float* WksA, float* WksB) {
    int i = blockIdx.x * blockDim.x + threadIdx.x;
    if (i < M0_R1)      degA[i] = 0;
    else if (i < M0_R2) degB[i - M0_R1] = 0;
    else if (i < M0_R3) { int j = i - M0_R2; cntA[j] = 0; curA[j] = 0; }
    else if (i < M0_R4) { int j = i - M0_R3; cntB[j] = 0; curB[j] = 0; }
    else if (i < M0_R5) seg_start_one(eb_batch, PE, i - M0_R4, segPA);
    else if (i < M0_R6) seg_start_one(nb_batch, PN, i - M0_R5, segPB);
    else if (i < M0_R7) {
        int j = i - M0_R6;
        if (j < 16384)       cvt_store(W1,  128, j, WAh, WAl, 0, 128);
        else if (j < 32768)  cvt_store(Wv1, 128, j - 16384, WAh, WAl, 128, 128);
        else if (j < 49152)  cvt_store(Wo1, 128, j - 32768, WO1h, WO1l, 0, 128);
        else if (j < 81920)  cvt_store(W2,  128, j - 49152, WBh, WBl, 0, 256);
        else if (j < 114688) cvt_store(Wv2, 128, j - 81920, WBh, WBl, 128, 256);
        else if (j < 131072) cvt_store(Wo2, 128, j - 114688, WO2h, WO2l, 0, 128);
        else if (j < 141312) cvt_store(clsW, 40, j - 131072, WCh, WCl, 0, 256);
        else if (j < 147456) {
            int q = j - 141312;
            size_t p = (size_t)(40 + q / 256) * 256 + (q % 256);
            WCh[p] = __float2bfloat16(0.f);
            WCl[p] = __float2bfloat16(0.f);
        }
        else if (j < 147968) fold_one(Wk1, sd1, WksA, j - 147456);
        else                 fold_one(Wk2, sd2, WksB, j - 147968);
    }
}

// ---------------- WMMA bf16 GEMM, 2-stage pipelined (hi/lo 3-term split) ----------------
// MODE 0: out0 cols<128, out1 cols>=128 (ld 128). MODE 1: relu -> out0 (ldc).
// MODE 2: bias+log-softmax over 40 cols -> out0[M,40].
struct XArgs {
    const int* dstA; const int* batA; int* degA; int* cntA;
    const int* dstB; const int* batB; int* degB; int* cntB;
    const float* X; const float* Wks; float* S; int M;
};

template<int KC, int NT, int MODE, int EXTRA>
__global__ void __launch_bounds__(256, 2)
wgemm_k(const float* __restrict__ A, int M,
        const __nv_bfloat16* __restrict__ Bhi, const __nv_bfloat16* __restrict__ Blo,
        const float* __restrict__ bias,
        float* __restrict__ out0, float* __restrict__ out1, int ldc,
        int gemmGX, XArgs xa) {
    if (EXTRA && blockIdx.x >= gemmGX) {
        if (blockIdx.y != 0) return;
        int id = (blockIdx.x - gemmGX) * 256 + threadIdx.x;
        if (EXTRA == 1) {
            if (id < ME) {
                int d = xa.dstA[id];
                atomicAdd(&xa.degA[d], 1);
                atomicAdd(&xa.cntA[xa.batA[d]], 1);
            } else if (id < ME + MN) {
                id -= ME;
                int d = xa.dstB[id];
                atomicAdd(&xa.degB[d], 1);
                atomicAdd(&xa.cntB[xa.batB[d]], 1);
            }
        } else {
            int gw = id >> 5;
            if (gw < xa.M) rowdot_body(xa.X, xa.Wks, xa.S, gw, 256, threadIdx.x & 31);
        }
        return;
    }

    constexpr int K = KC * 16;
    constexpr int WN = NT / 2;
    constexpr int NTI = WN / 16;
    constexpr int NTS = NT + 4;
    constexpr int STG_E = (256 + 2 * NT) * 24;

    extern __shared__ char smc[];
    __nv_bfloat16* sb = (__nv_bfloat16*)smc;
    float* stg = (float*)smc;

    int tid = threadIdx.x;
    int wid = tid >> 5;
    int wm = wid >> 1, wn = wid & 1;
    int row0 = blockIdx.x * 128;
    int col0 = blockIdx.y * NT;

    int ar = tid >> 1, akk = (tid & 1) * 8;
    int gr = row0 + ar;
    const float* aptr = (gr < M) ? (A + (size_t)gr * K + akk) : nullptr;

    wmma::fragment<wmma::accumulator, 16, 16, 16, float> acc[2][NTI];
    #pragma unroll
    for (int m = 0; m < 2; m++)
        #pragma unroll
        for (int n = 0; n < NTI; n++) wmma::fill_fragment(acc[m][n], 0.0f);

    float4 pv0, pv1;
    {
        pv0 = make_float4(0.f, 0.f, 0.f, 0.f); pv1 = pv0;
        if (aptr) { pv0 = *(const float4*)aptr; pv1 = *(const float4*)(aptr + 4); }
        __nv_bfloat16* sBh0 = sb + 256 * 24;
        __nv_bfloat16* sBl0 = sBh0 + NT * 24;
        for (int i = tid; i < NT * 2; i += 256) {
            int n = i >> 1, kk = (i & 1) * 8;
            size_t g = (size_t)(col0 + n) * K + kk;
            cp16(&sBh0[n * 24 + kk], Bhi + g);
            cp16(&sBl0[n * 24 + kk], Blo + g);
        }
        CP_COMMIT();
        float vv[8] = {pv0.x, pv0.y, pv0.z, pv0.w, pv1.x, pv1.y, pv1.z, pv1.w};
        uint4 hp, lp;
        pack_hilo(vv, hp, lp);
        *(uint4*)&sb[ar * 24 + akk] = hp;
        *(uint4*)&sb[128 * 24 + ar * 24 + akk] = lp;
    }

    for (int kc = 0; kc < KC; kc++) {
        int buf = kc & 1;
        __nv_bfloat16* sAh = sb + buf * STG_E;
        __nv_bfloat16* sAl = sAh + 128 * 24;
        __nv_bfloat16* sBh = sAl + 128 * 24;
        __nv_bfloat16* sBl = sBh + NT * 24;
        CP_WAIT0();
        __syncthreads();

        if (kc + 1 < KC) {
            pv0 = make_float4(0.f, 0.f, 0.f, 0.f); pv1 = pv0;
            if (aptr) {
                const float* ap = aptr + (kc + 1) * 16;
                pv0 = *(const float4*)ap; pv1 = *(const float4*)(ap + 4);
            }
            __nv_bfloat16* nBh = sb + (buf ^ 1) * STG_E + 256 * 24;
            __nv_bfloat16* nBl = nBh + NT * 24;
            for (int i = tid; i < NT * 2; i += 256) {
                int n = i >> 1, kk = (i & 1) * 8;
                size_t g = (size_t)(col0 + n) * K + (kc + 1) * 16 + kk;
                cp16(&nBh[n * 24 + kk], Bhi + g);
                cp16(&nBl[n * 24 + kk], Blo + g);
            }
            CP_COMMIT();
        }

        wmma::fragment<wmma::matrix_a, 16, 16, 16, __nv_bfloat16, wmma::row_major> ah[2], al[2];
        #pragma unroll
        for (int m = 0; m < 2; m++) {
            wmma::load_matrix_sync(ah[m], sAh + (wm * 32 + m * 16) * 24, 24);
            wmma::load_matrix_sync(al[m], sAl + (wm * 32 + m * 16) * 24, 24);
        }
        #pragma unroll
        for (int n = 0; n < NTI; n++) {
            wmma::fragment<wmma::matrix_b, 16, 16, 16, __nv_bfloat16, wmma::col_major> bh, bl;
            wmma::load_matrix_sync(bh, sBh + (wn * WN + n * 16) * 24, 24);
            wmma::load_matrix_sync(bl, sBl + (wn * WN + n * 16) * 24, 24);
            #pragma unroll
            for (int m = 0; m < 2; m++) {
                wmma::mma_sync(acc[m][n], ah[m], bh, acc[m][n]);
                wmma::mma_sync(acc[m][n], ah[m], bl, acc[m][n]);
                wmma::mma_sync(acc[m][n], al[m], bh, acc[m][n]);
            }
        }

        if (kc + 1 < KC) {
            __nv_bfloat16* nAh = sb + (buf ^ 1) * STG_E;
            __nv_bfloat16* nAl = nAh + 128 * 24;
            float vv[8] = {pv0.x, pv0.y, pv0.z, pv0.w, pv1.x, pv1.y, pv1.z, pv1.w};
            uint4 hp, lp;
            pack_hilo(vv, hp, lp);
            *(uint4*)&nAh[ar * 24 + akk] = hp;
            *(uint4*)&nAl[ar * 24 + akk] = lp;
        }
    }
    __syncthreads();

    if (MODE == 2) {
        #pragma unroll
        for (int m = 0; m < 2; m++)
            #pragma unroll
            for (int n = 0; n < NTI; n++)
                wmma::store_matrix_sync(stg + (wm * 32 + m * 16) * NTS + wn * WN + n * 16,
                                        acc[m][n], NTS, wmma::mem_row_major);
        __syncthreads();
        if (tid < 128) {
            int r = row0 + tid;
            if (r < M) {
                const float* row = stg + tid * NTS;
                float v[40];
                float mx = -CUDART_INF_F;
                #pragma unroll
                for (int c = 0; c < 40; c++) { v[c] = row[c] + bias[c]; mx = fmaxf(mx, v[c]); }
                float s = 0.f;
                #pragma unroll
                for (int c = 0; c < 40; c++) s += expf(v[c] - mx);
                float lse = mx + logf(s);
                #pragma unroll
                for (int c = 0; c < 40; c += 4) {
                    float4 f = make_float4(v[c] - lse, v[c+1] - lse, v[c+2] - lse, v[c+3] - lse);
                    *(float4*)&out0[(size_t)r * 40 + c] = f;
                }
            }
        }
    } else {
        #pragma unroll
        for (int m = 0; m < 2; m++) {
            int gr0 = row0 + wm * 32 + m * 16;
            #pragma unroll
            for (int n = 0; n < NTI; n++) {
                int gc = col0 + wn * WN + n * 16;
                if (MODE == 1) {
                    #pragma unroll
                    for (int t = 0; t < acc[m][n].num_elements; t++)
                        acc[m][n].x[t] = fmaxf(acc[m][n].x[t], 0.f);
                    wmma::store_matrix_sync(out0 + (size_t)gr0 * ldc + gc, acc[m][n],
                                            ldc, wmma::mem_row_major);
                } else {
                    float* dst = (gc < 128) ? (out0 + (size_t)gr0 * 128 + gc)
                                            : (out1 + (size_t)gr0 * 128 + gc - 128);
                    wmma::store_matrix_sync(dst, acc[m][n], 128, wmma::mem_row_major);
                }
            }
        }
    }
}

// ---------------- misc1 / fin2 / scatter ----------------
constexpr int NBA = (NE + 1023) / 1024;
constexpr int NBB = (NN + 1023) / 1024;
constexpr int DINV_B = (PE + PN + 1023) / 1024;
constexpr int RDA_B = (NN + 31) / 32;

__device__ __forceinline__ void scan_body(const int* __restrict__ cnt, int n,
                                          int* __restrict__ incl, int* __restrict__ bsums,
                                          int b) {
    __shared__ int sm[1024];
    int i = b * 1024 + threadIdx.x;
    int v = (i < n) ? cnt[i] : 0;
    sm[threadIdx.x] = v;
    __syncthreads();
    for (int o = 1; o < 1024; o <<= 1) {
        int t = (threadIdx.x >= o) ? sm[threadIdx.x - o] : 0;
        __syncthreads();
        sm[threadIdx.x] += t;
        __syncthreads();
    }
    if (i < n) incl[i] = sm[threadIdx.x];
    if (threadIdx.x == 1023) bsums[b] = sm[1023];
}

__global__ void misc1_k(const int* __restrict__ cntA, int* inclA, int* bsumA,
                        const int* __restrict__ cntB, int* inclB, int* bsumB,
                        const int* __restrict__ degA, float* dinvA,
                        const int* __restrict__ degB, float* dinvB,
                        const float* __restrict__ X, const float* __restrict__ Wks,
                        float* S) {
    int b = blockIdx.x;
    if (b < NBA) { scan_body(cntA, NE, inclA, bsumA, b); return; }
    b -= NBA;
    if (b < NBB) { scan_body(cntB, NN, inclB, bsumB, b); return; }
    b -= NBB;
    if (b < DINV_B) {
        int i = b * 1024 + threadIdx.x;
        if (i < PE) dinvA[i] = rsqrtf((float)(degA[i] + 1));
        else if (i < PE + PN) dinvB[i - PE] = rsqrtf((float)(degB[i - PE] + 1));
        return;
    }
    b -= DINV_B;
    int gw = b * 32 + (threadIdx.x >> 5);
    if (gw < NN) rowdot_body(X, Wks, S, gw, 128, threadIdx.x & 31);
}

__global__ void fin2_k(const int* __restrict__ inclA, const int* __restrict__ bsumA, int* offA,
                       const int* __restrict__ inclB, const int* __restrict__ bsumB, int* offB) {
    __shared__ int pfx;
    int b = blockIdx.x;
    if (b < NBA) {
        if (threadIdx.x == 0) {
            int s = 0;
            for (int t = 0; t < b; t++) s += bsumA[t];
            pfx = s;
        }
        __syncthreads();
        int i = b * 1024 + threadIdx.x;
        if (i < NE) offA[i + 1] = inclA[i] + pfx;
        if (i == 0) offA[0] = 0;
    } else {
        b -= NBA;
        if (threadIdx.x == 0) {
            int s = 0;
            for (int t = 0; t < b; t++) s += bsumB[t];
            pfx = s;
        }
        __syncthreads();
        int i = b * 1024 + threadIdx.x;
        if (i < NN) offB[i + 1] = inclB[i] + pfx;
        if (i == 0) offB[0] = 0;
    }
}

__device__ __forceinline__ void scatter_one(const int* src, const int* dst, const int* batch,
                                            const int* map, const float* dinv, const int* off,
                                            int* cursor, int i, int* outG, float* outW) {
    int d = dst[i];
    int s = batch[d];
    int pos = off[s] + atomicAdd(&cursor[s], 1);
    int sc = src[i];
    outG[pos] = map[sc];
    outW[pos] = dinv[sc] * dinv[d];
}

__global__ void scatterA_k(const int* eb_ei, const int* eb_batch, const int* eb_map,
                           const float* dinvA, const int* offA, int* curA,
                           int* srtGA, float* srtWA) {
    int i = blockIdx.x * blockDim.x + threadIdx.x;
    if (i < ME)
        scatter_one(eb_ei, eb_ei + ME, eb_batch, eb_map, dinvA, offA, curA, i, srtGA, srtWA);
}

// ---------------- fused per-segment: GCN-conv mean + PMA softmax pool ----------------
// Warp per segment; MLP unrolls; optional scatter-B piggyback on extra blocks.
struct SBArgs {
    const int* src; const int* dst; const int* batch; const int* map;
    const float* dinv; const int* off; int* cur; int* outG; float* outW;
};

__global__ void __launch_bounds__(256)
seg_fused_k(const float* __restrict__ H, const float* __restrict__ V,
            const float* __restrict__ S4, const int* __restrict__ map,
            const float* __restrict__ dinv,
            const int* __restrict__ segP, const int* __restrict__ eOff,
            const int* __restrict__ sG, const float* __restrict__ sW,
            const float* __restrict__ bias,
            float* __restrict__ outConv, int ldOut,
            float* __restrict__ pooled, int S,
            int gxSeg, SBArgs sb2) {
    if (sb2.dst && blockIdx.x >= gxSeg) {
        int i = (blockIdx.x - gxSeg) * 256 + threadIdx.x;
        if (i < MN)
            scatter_one(sb2.src, sb2.dst, sb2.batch, sb2.map, sb2.dinv, sb2.off,
                        sb2.cur, i, sb2.outG, sb2.outW);
        return;
    }

    int w = (blockIdx.x * blockDim.x + threadIdx.x) >> 5;
    if (w >= S) return;
    int lane = threadIdx.x & 31;
    int h = lane >> 3;
    int sub = lane & 7;
    int s = w;
    const float4* H4 = (const float4*)H;
    const float4* V4 = (const float4*)V;

    int p0 = segP[s], p1 = segP[s + 1];
    int e0 = eOff[s], e1 = eOff[s + 1];

    float4 acc = make_float4(0.f, 0.f, 0.f, 0.f);
    int j = e0;
    for (; j + 7 < e1; j += 8) {
        int g[8];
        float wt[8];
        #pragma unroll
        for (int q = 0; q < 8; q++) { g[q] = sG[j + q]; wt[q] = sW[j + q]; }
        float4 hv[8];
        #pragma unroll
        for (int q = 0; q < 8; q++) hv[q] = H4[(size_t)g[q] * 32 + lane];
        #pragma unroll
        for (int q = 0; q < 8; q++) {
            acc.x += hv[q].x * wt[q];
            acc.y += hv[q].y * wt[q];
            acc.z += hv[q].z * wt[q];
            acc.w += hv[q].w * wt[q];
        }
    }
    for (; j < e1; j++) {
        int g = sG[j]; float wt = sW[j];
        float4 hv = H4[(size_t)g * 32 + lane];
        acc.x += hv.x * wt; acc.y += hv.y * wt; acc.z += hv.z * wt; acc.w += hv.w * wt;
    }

    float m = -CUDART_INF_F;
    for (int p = p0 + sub; p < p1; p += 8)
        m = fmaxf(m, S4[(size_t)map[p] * 4 + h]);
    #pragma unroll
    for (int o = 1; o < 8; o <<= 1)
        m = fmaxf(m, __shfl_xor_sync(0xffffffffu, m, o));

    float den = 0.f;
    float4 pv = make_float4(0.f, 0.f, 0.f, 0.f);
    int p = p0;
    for (; p + 3 < p1; p += 4) {
        int g[4];
        float wt[4], e[4];
        #pragma unroll
        for (int q = 0; q < 4; q++) {
            g[q] = map[p + q];
            float d = dinv[p + q];
            wt[q] = d * d;
        }
        float4 hv[4], vv[4];
        #pragma unroll
        for (int q = 0; q < 4; q++) {
            hv[q] = H4[(size_t)g[q] * 32 + lane];
            vv[q] = V4[(size_t)g[q] * 32 + lane];
        }
        #pragma unroll
        for (int q = 0; q < 4; q++) {
            e[q] = __expf(S4[(size_t)g[q] * 4 + h] - m);
            den += e[q];
        }
        #pragma unroll
        for (int q = 0; q < 4; q++) {
            acc.x += hv[q].x * wt[q];  pv.x += vv[q].x * e[q];
            acc.y += hv[q].y * wt[q];  pv.y += vv[q].y * e[q];
            acc.z += hv[q].z * wt[q];  pv.z += vv[q].z * e[q];
            acc.w += hv[q].w * wt[q];  pv.w += vv[q].w * e[q];
        }
    }
    for (; p < p1; p++) {
        int g = map[p];
        float d = dinv[p];
        float wt = d * d;
        float e = __expf(S4[(size_t)g * 4 + h] - m);
        den += e;
        float4 hv = H4[(size_t)g * 32 + lane];
        float4 vv = V4[(size_t)g * 32 + lane];
        acc.x += hv.x * wt;  pv.x += vv.x * e;
        acc.y += hv.y * wt;  pv.y += vv.y * e;
        acc.z += hv.z * wt;  pv.z += vv.z * e;
        acc.w += hv.w * wt;  pv.w += vv.w * e;
    }

    int cnt = p1 - p0;
    float4 ob;
    if (cnt > 0) {
        float inv = 1.f / (float)cnt;
        float4 b4 = *(const float4*)&bias[lane * 4];
        ob.x = fmaxf(acc.x * inv + b4.x, 0.f);
        ob.y = fmaxf(acc.y * inv + b4.y, 0.f);
        ob.z = fmaxf(acc.z * inv + b4.z, 0.f);
        ob.w = fmaxf(acc.w * inv + b4.w, 0.f);
    } else {
        ob = make_float4(0.f, 0.f, 0.f, 0.f);
    }
    *(float4*)&outConv[(size_t)s * ldOut + lane * 4] = ob;

    float dn = 1.f / fmaxf(den, 1e-9f);
    float4 op;
    op.x = pv.x * dn; op.y = pv.y * dn; op.z = pv.z * dn; op.w = pv.w * dn;
    if (cnt == 0) op = make_float4(0.f, 0.f, 0.f, 0.f);
    *(float4*)&pooled[(size_t)s * 128 + lane * 4] = op;
}

// ---------------- orchestration (single stream, graph-safe) ----------------
static inline int cdiv(int a, int b) { return (a + b - 1) / b; }

extern "C" void kernel_launch(void* const* d_in, const int* in_sizes, int n_in,
                              void* d_out, int out_size) {
    (void)in_sizes; (void)n_in; (void)out_size;
    const float* node_x  = (const float*)d_in[0];
    const int* eb_map    = (const int*)d_in[1];
    const int* eb_ei     = (const int*)d_in[2];
    const int* eb_batch  = (const int*)d_in[3];
    const int* nb_map    = (const int*)d_in[4];
    const int* nb_ei     = (const int*)d_in[5];
    const int* nb_batch  = (const int*)d_in[6];
    const float* W1   = (const float*)d_in[7];
    const float* b1   = (const float*)d_in[8];
    const float* Wk1  = (const float*)d_in[9];
    const float* Wv1  = (const float*)d_in[10];
    const float* sd1  = (const float*)d_in[11];
    const float* Wo1  = (const float*)d_in[12];
    const float* W2   = (const float*)d_in[13];
    const float* b2   = (const float*)d_in[14];
    const float* Wk2  = (const float*)d_in[15];
    const float* Wv2  = (const float*)d_in[16];
    const float* sd2  = (const float*)d_in[17];
    const float* Wo2  = (const float*)d_in[18];
    const float* clsW = (const float*)d_in[19];
    const float* clsb = (const float*)d_in[20];
    float* out = (float*)d_out;

    void* basep = nullptr;
    cudaGetSymbolAddress(&basep, g_scratch);
    char* base = (char*)basep;
    float* nodeH  = (float*)(base + O_NODEH);
    float* nodeV  = (float*)(base + O_NODEV);
    float* nodeS  = (float*)(base + O_NODES);
    int*   degA   = (int*)  (base + O_DEGA);
    float* dinvA  = (float*)(base + O_DINVA);
    int*   segPA  = (int*)  (base + O_SEGPA);
    int*   cntA   = (int*)  (base + O_CNTA);
    int*   offA   = (int*)  (base + O_OFFA);
    int*   curA   = (int*)  (base + O_CURA);
    int*   srtGA  = (int*)  (base + O_SRTGA);
    float* srtWA  = (float*)(base + O_SRTWA);
    float* poolA  = (float*)(base + O_POOLA);
    float* edgeX  = (float*)(base + O_EDGEX);
    float* edgeH  = (float*)(base + O_EDGEH);
    float* edgeV  = (float*)(base + O_EDGEV);
    float* edgeS  = (float*)(base + O_EDGES);
    int*   degB   = (int*)  (base + O_DEGB);
    float* dinvB  = (float*)(base + O_DINVB);
    int*   segPB  = (int*)  (base + O_SEGPB);
    int*   cntB   = (int*)  (base + O_CNTB);
    int*   offB   = (int*)  (base + O_OFFB);
    int*   curB   = (int*)  (base + O_CURB);
    int*   srtGB  = (int*)  (base + O_SRTGB);
    float* srtWB  = (float*)(base + O_SRTWB);
    float* poolB  = (float*)(base + O_POOLB);
    float* nodeO  = (float*)(base + O_NODEO);
    float* WksA   = (float*)(base + O_WKSA);
    float* WksB   = (float*)(base + O_WKSB);
    int*   inclA  = (int*)  (base + O_INCLA);
    int*   bsumA  = (int*)  (base + O_BSUMA);
    int*   inclB  = (int*)  (base + O_INCLB);
    int*   bsumB  = (int*)  (base + O_BSUMB);
    __nv_bfloat16* WAh  = (__nv_bfloat16*)(base + O_WAH);
    __nv_bfloat16* WAl  = (__nv_bfloat16*)(base + O_WAL);
    __nv_bfloat16* WO1h = (__nv_bfloat16*)(base + O_WO1H);
    __nv_bfloat16* WO1l = (__nv_bfloat16*)(base + O_WO1L);
    __nv_bfloat16* WBh  = (__nv_bfloat16*)(base + O_WBH);
    __nv_bfloat16* WBl  = (__nv_bfloat16*)(base + O_WBL);
    __nv_bfloat16* WO2h = (__nv_bfloat16*)(base + O_WO2H);
    __nv_bfloat16* WO2l = (__nv_bfloat16*)(base + O_WO2L);
    __nv_bfloat16* WCh  = (__nv_bfloat16*)(base + O_WCH);
    __nv_bfloat16* WCl  = (__nv_bfloat16*)(base + O_WCL);

    constexpr int SMAB128 = 2 * (256 + 2 * 128) * 24 * 2;  // 49152
    constexpr int SMCLS   = 2 * (256 + 2 * 64) * 24 * 2;   // 36864
    cudaFuncSetAttribute(wgemm_k<8, 128, 0, 1>,  cudaFuncAttributeMaxDynamicSharedMemorySize, SMAB128);
    cudaFuncSetAttribute(wgemm_k<8, 128, 1, 0>,  cudaFuncAttributeMaxDynamicSharedMemorySize, SMAB128);
    cudaFuncSetAttribute(wgemm_k<16, 128, 0, 2>, cudaFuncAttributeMaxDynamicSharedMemorySize, SMAB128);
    cudaFuncSetAttribute(wgemm_k<16, 64, 2, 0>,  cudaFuncAttributeMaxDynamicSharedMemorySize, SMCLS);

    XArgs xnone = {};
    XArgs xdeg = { eb_ei + ME, eb_batch, degA, cntA,
                   nb_ei + MN, nb_batch, degB, cntB,
                   nullptr, nullptr, nullptr, 0 };
    XArgs xrdB = { nullptr, nullptr, nullptr, nullptr,
                   nullptr, nullptr, nullptr, nullptr,
                   edgeX, WksB, edgeS, NE };
    SBArgs sbNone = {};
    SBArgs sbB = { nb_ei, nb_ei + MN, nb_batch, nb_map, dinvB, offB, curB, srtGB, srtWB };

    // L1: init + seg_starts + all weight prep
    misc0_k<<<cdiv(M0_R7, 256), 256>>>(eb_batch, nb_batch,
                                       degA, cntA, curA, degB, cntB, curB, segPA, segPB,
                                       W1, Wv1, Wo1, W2, Wv2, Wo2, clsW,
                                       Wk1, sd1, Wk2, sd2,
                                       WAh, WAl, WO1h, WO1l, WBh, WBl,
                                       WO2h, WO2l, WCh, WCl, WksA, WksB);

    // L2: stage-A GEMM  ∥  degcount (both stages)
    {
        int gx = cdiv(NN, 128);
        int extra = cdiv(ME + MN, 256);
        dim3 g(gx + extra, 2);
        wgemm_k<8, 128, 0, 1><<<g, 256, SMAB128>>>(node_x, NN, WAh, WAl, nullptr,
                                                   nodeH, nodeV, 0, gx, xdeg);
    }

    // L3: both scans + both dinv + rowdot4-A
    misc1_k<<<NBA + NBB + DINV_B + RDA_B, 1024>>>(cntA, inclA, bsumA, cntB, inclB, bsumB,
                                                  degA, dinvA, degB, dinvB,
                                                  node_x, WksA, nodeS);
    // L4: finalize offsets
    fin2_k<<<NBA + NBB, 1024>>>(inclA, bsumA, offA, inclB, bsumB, offB);

    // L5: scatter A only
    scatterA_k<<<cdiv(ME, 256), 256>>>(eb_ei, eb_batch, eb_map, dinvA, offA, curA,
                                       srtGA, srtWA);

    // L6: stage-A fused segment kernel  ∥  scatter B piggyback
    {
        int gxSeg = cdiv(NE * 32, 256);
        int extra = cdiv(MN, 256);
        seg_fused_k<<<gxSeg + extra, 256>>>(nodeH, nodeV, nodeS, eb_map, dinvA, segPA, offA,
                                            srtGA, srtWA, b1, edgeX, 256, poolA, NE,
                                            gxSeg, sbB);
    }
    // L7: Wo1
    {
        int gx = cdiv(NE, 128);
        dim3 g(gx, 1);
        wgemm_k<8, 128, 1, 0><<<g, 256, SMAB128>>>(poolA, NE, WO1h, WO1l, nullptr,
                                                   edgeX + 128, nullptr, 256, gx, xnone);
    }

    // L8: stage-B GEMM  ∥  rowdot4-B
    {
        int gx = cdiv(NE, 128);
        int extra = cdiv(NE * 32, 256);
        dim3 g(gx + extra, 2);
        wgemm_k<16, 128, 0, 2><<<g, 256, SMAB128>>>(edgeX, NE, WBh, WBl, nullptr,
                                                    edgeH, edgeV, 0, gx, xrdB);
    }

    // L9: stage-B fused segment kernel (conv -> nodeO interleaved ld 256)
    {
        int gxSeg = cdiv(NN * 32, 256);
        seg_fused_k<<<gxSeg, 256>>>(edgeH, edgeV, edgeS, nb_map, dinvB, segPB, offB,
                                    srtGB, srtWB, b2, nodeO, 256, poolB, NN,
                                    gxSeg, sbNone);
    }
    // L10: Wo2
    {
        int gx = cdiv(NN, 128);
        dim3 g(gx, 1);
        wgemm_k<8, 128, 1, 0><<<g, 256, SMAB128>>>(poolB, NN, WO2h, WO2l, nullptr,
                                                   nodeO + 128, nullptr, 256, gx, xnone);
    }

    // L11: classifier + fused log-softmax
    {
        int gx = cdiv(NN, 128);
        dim3 g(gx, 1);
        wgemm_k<16, 64, 2, 0><<<g, 256, SMCLS>>>(nodeO, NN, WCh, WCl, clsb,
                                                 out, nullptr, 40, gx, xnone);
    }
}